// round 5
// baseline (speedup 1.0000x reference)
#include <cuda_runtime.h>
#include <cuda_bf16.h>
#include <cstdint>

// ============================================================================
// Problem constants
// ============================================================================
#define NQ      4096
#define NREF    65536
#define DIMK    512
#define TOPK    16
#define NCTA    148                    // persistent CTAs (one wave)
#define NMB     32                     // query mblocks of 128
#define SPANS_PER_MB 64                // span = 1024 refs = 8 tiles of 128
#define TOTAL_UNITS (NMB * SPANS_PER_MB)   // 2048
#define E_SLOTS 8                      // max CTAs covering one mblock

// SMEM layout (byte offsets into dynamic smem)
#define SM_A      0                    // 128 x 512 bf16 (swizzled)    131072
#define SM_B      131072               // 2 x (128 x 64 bf16 swizzled)  32768
#define SM_STAGE  163840               // 2 x (128 x 64 fp32 swizzled)  65536
#define SMEM_TOTAL 229376

// ============================================================================
// Scratch (static device arrays; no allocation anywhere)
// ============================================================================
__device__ __align__(16) __nv_bfloat16 g_refs_bf16[(size_t)NREF * DIMK]; // 64 MB
__device__ __align__(16) __nv_bfloat16 g_xn[(size_t)NQ * DIMK];          // 4 MB
__device__ __align__(16) float g_part[(size_t)NQ * E_SLOTS * TOPK];      // 2 MB

// ============================================================================
// Helpers (baseline sm_103 ISA only)
// ============================================================================
__device__ __forceinline__ uint32_t smem_u32(const void* p) {
    return (uint32_t)__cvta_generic_to_shared(p);
}

__device__ __forceinline__ void cp_async_16(uint32_t dst, const void* src) {
    asm volatile("cp.async.cg.shared.global [%0], [%1], 16;"
                 :: "r"(dst), "l"((unsigned long long)__cvta_generic_to_global(src)) : "memory");
}
#define CP_COMMIT() asm volatile("cp.async.commit_group;" ::: "memory")
#define CP_WAIT(N)  asm volatile("cp.async.wait_group %0;" :: "n"(N) : "memory")

__device__ __forceinline__ void ldsm_x4(uint32_t* r, uint32_t addr) {
    asm volatile("ldmatrix.sync.aligned.m8n8.x4.shared.b16 {%0,%1,%2,%3}, [%4];"
                 : "=r"(r[0]), "=r"(r[1]), "=r"(r[2]), "=r"(r[3]) : "r"(addr));
}

__device__ __forceinline__ void mma16816(float* c, const uint32_t* a, const uint32_t* b) {
    asm volatile("mma.sync.aligned.m16n8k16.row.col.f32.bf16.bf16.f32 "
                 "{%0,%1,%2,%3}, {%4,%5,%6,%7}, {%8,%9}, {%0,%1,%2,%3};"
                 : "+f"(c[0]), "+f"(c[1]), "+f"(c[2]), "+f"(c[3])
                 : "r"(a[0]), "r"(a[1]), "r"(a[2]), "r"(a[3]), "r"(b[0]), "r"(b[1]));
}

__device__ __forceinline__ void topk_insert(float v, float* top, float& thr) {
    if (v > thr) {
        int mi = 0; float mv = top[0];
#pragma unroll
        for (int i = 1; i < TOPK; i++)
            if (top[i] < mv) { mv = top[i]; mi = i; }
        top[mi] = v;
        mv = top[0];
#pragma unroll
        for (int i = 1; i < TOPK; i++) mv = fminf(mv, top[i]);
        thr = mv;
    }
}

// Balanced static partition of TOTAL_UNITS over NCTA CTAs
__device__ __forceinline__ int unit_begin(int c) { return (c * TOTAL_UNITS) / NCTA; }
__device__ __forceinline__ int cta_of_unit(int u) {
    int c = (u * NCTA) / TOTAL_UNITS;
    while (unit_begin(c + 1) <= u) c++;
    while (unit_begin(c) > u) c--;
    return c;
}

// ============================================================================
// Kernel 1: L2-normalize x (fp32) -> g_xn (bf16)
// ============================================================================
__global__ void k_norm(const float* __restrict__ x) {
    int row = blockIdx.x;
    int tid = threadIdx.x;   // 128
    float v[4];
    float ss = 0.f;
#pragma unroll
    for (int j = 0; j < 4; j++) {
        v[j] = x[(size_t)row * DIMK + tid + j * 128];
        ss += v[j] * v[j];
    }
#pragma unroll
    for (int o = 16; o; o >>= 1) ss += __shfl_xor_sync(0xFFFFFFFFu, ss, o);
    __shared__ float sred[4];
    if ((tid & 31) == 0) sred[tid >> 5] = ss;
    __syncthreads();
    float tot = sred[0] + sred[1] + sred[2] + sred[3];
    float inv = 1.0f / fmaxf(sqrtf(tot), 1e-12f);
#pragma unroll
    for (int j = 0; j < 4; j++)
        g_xn[(size_t)row * DIMK + tid + j * 128] = __float2bfloat16(v[j] * inv);
}

// ============================================================================
// Kernel 2: refs fp32 -> bf16
// ============================================================================
__global__ void k_cvt(const float* __restrict__ refs) {
    int n = NREF * DIMK / 4;
    const float4* src = (const float4*)refs;
    __nv_bfloat162* dst = (__nv_bfloat162*)g_refs_bf16;
    for (int i = blockIdx.x * blockDim.x + threadIdx.x; i < n; i += gridDim.x * blockDim.x) {
        float4 v = src[i];
        dst[2 * i]     = __floats2bfloat162_rn(v.x, v.y);
        dst[2 * i + 1] = __floats2bfloat162_rn(v.z, v.w);
    }
}

// ============================================================================
// Kernel 2b: reset partial-list slots to -2 (required every graph replay)
// ============================================================================
__global__ void k_fill() {
    int i = blockIdx.x * blockDim.x + threadIdx.x;
    ((float4*)g_part)[i] = make_float4(-2.f, -2.f, -2.f, -2.f);
}

// ============================================================================
// Kernel 3: warp-specialized persistent bf16 GEMM + fused streaming top-16
//   148 CTAs x 384 threads:
//     warps 0-7 : compute (2M x 4N of 64x32 tiles), mma only
//     warps 8-11: aux — cp.async B producer + stage scanner (1 thread/row)
// ============================================================================
__global__ __launch_bounds__(384, 1) void k_main() {
    extern __shared__ char smem[];
    const uint32_t sb = smem_u32(smem);
    const int tid = threadIdx.x, wid = tid >> 5, lid = tid & 31;
    const bool is_aux = (wid >= 8);
    const int mw = wid >> 2, nw = wid & 3;          // compute warps only
    const int c = blockIdx.x;

    // ---- compute-warp ldmatrix address components ---------------------------
    const uint32_t swz = (uint32_t)(lid & 7) << 4;
    const int sub = lid >> 3;
    const int aRow = mw * 64 + (lid & 7) + ((sub & 1) << 3);
    const uint32_t a_kof2 = (uint32_t)(sub >> 1) << 4;
    const uint32_t aBase = sb + SM_A + (uint32_t)aRow * 1024u;
    const int bRow = nw * 32 + (lid & 7) + ((sub >> 1) << 3);
    const uint32_t b_kof2 = (uint32_t)(sub & 1) << 4;
    const uint32_t bRowByte = (uint32_t)bRow * 128u;     // 128B rows (64 bf16)

    // ---- aux state ----------------------------------------------------------
    const int r = tid - 256;                              // 0..127 (aux row)
    float top[TOPK];
    float thr = -2.0f;
#pragma unroll
    for (int i = 0; i < TOPK; i++) top[i] = -2.0f;

    // ---- compute state ------------------------------------------------------
    float acc[4][4][4];

    int u = unit_begin(c);
    const int u_end = unit_begin(c + 1);

#pragma unroll 1
    while (u < u_end) {
        const int mb = u >> 6;
        const int seg_end = min(u_end, (mb + 1) << 6);
        const int nch = (seg_end - u) * 64;              // 64 chunks per span
        const int span0 = u & 63;

        if (!is_aux) {
            // ---- load A tile (128 x 512 bf16, swizzled) ---------------------
            int row = tid >> 1, seg = tid & 1;
            const uint4* src = (const uint4*)(g_xn + ((size_t)(mb * 128 + row)) * DIMK + seg * 256);
            uint32_t swzr = (uint32_t)(row & 7) << 4;
            char* dstrow = smem + SM_A + row * 1024;
#pragma unroll
            for (int j = 0; j < 32; j++) {
                uint32_t off = (uint32_t)(seg * 512 + j * 16);
                *(uint4*)(dstrow + (off ^ swzr)) = src[j];
            }
#pragma unroll
            for (int a = 0; a < 4; a++)
#pragma unroll
                for (int b = 0; b < 4; b++)
#pragma unroll
                    for (int d = 0; d < 4; d++) acc[a][b][d] = 0.f;
        } else {
            // ---- prefetch chunk 0 (tile 0, kc 0) ----------------------------
            const char* src = (const char*)g_refs_bf16 +
                ((size_t)(span0 * 1024 + r)) * 1024;
            uint32_t dst = sb + SM_B + (uint32_t)r * 128u;
            uint32_t swzr = (uint32_t)(r & 7) << 4;
#pragma unroll
            for (int j = 0; j < 8; j++)
                cp_async_16(dst + (((uint32_t)(j * 16)) ^ swzr), src + j * 16);
            CP_COMMIT();
            CP_WAIT(0);
        }
        __syncthreads();

#pragma unroll 1
        for (int ch = 0; ch < nch; ch++) {
            if (is_aux) {
                // ---- producer: issue chunk ch+1 -----------------------------
                if (ch + 1 < nch) {
                    int ch2 = ch + 1;
                    int t2 = ch2 >> 3, kc2 = ch2 & 7;
                    const char* src = (const char*)g_refs_bf16 +
                        ((size_t)(span0 * 1024 + t2 * 128 + r)) * 1024 + kc2 * 128;
                    uint32_t dst = sb + SM_B + (uint32_t)(ch2 & 1) * 16384u + (uint32_t)r * 128u;
                    uint32_t swzr = (uint32_t)(r & 7) << 4;
#pragma unroll
                    for (int j = 0; j < 8; j++)
                        cp_async_16(dst + (((uint32_t)(j * 16)) ^ swzr), src + j * 16);
                    CP_COMMIT();
                }
                // ---- scanner: previous tile's stage slot --------------------
                if (ch >= 8 && (ch & 7) < 2) {
                    int s = ch & 7;                       // slot 0 then 1
                    const char* base = smem + SM_STAGE + s * 32768 + r * 256;
                    uint32_t rsw = (uint32_t)(r & 7) << 4;
                    int rot = r & 15;
#pragma unroll
                    for (int jj = 0; jj < 16; jj++) {
                        uint32_t cidx = (uint32_t)((jj + rot) & 15);
                        float4 v = *(const float4*)(base + ((cidx * 16u) ^ rsw));
                        topk_insert(v.x, top, thr);
                        topk_insert(v.y, top, thr);
                        topk_insert(v.z, top, thr);
                        topk_insert(v.w, top, thr);
                    }
                }
                CP_WAIT(0);
            } else {
                // ---- compute: chunk ch = 4 mma k-steps, sw-pipelined --------
                const uint32_t aoff = (uint32_t)(ch & 7) * 128u;
                const uint32_t bbase = sb + SM_B + (uint32_t)(ch & 1) * 16384u + bRowByte;
                uint32_t afr[2][4][4];
                uint32_t bfr[2][2][4];
#pragma unroll
                for (int mt = 0; mt < 4; mt++)
                    ldsm_x4(afr[0][mt], aBase + (uint32_t)mt * 16384u +
                            ((aoff + a_kof2) ^ swz));
#pragma unroll
                for (int j = 0; j < 2; j++)
                    ldsm_x4(bfr[0][j], bbase + (uint32_t)j * 2048u + (b_kof2 ^ swz));
#pragma unroll
                for (int ks = 0; ks < 4; ks++) {
                    const int cur = ks & 1, nxt = cur ^ 1;
                    if (ks < 3) {
                        uint32_t ko = (uint32_t)(ks + 1) * 32u;
#pragma unroll
                        for (int mt = 0; mt < 4; mt++)
                            ldsm_x4(afr[nxt][mt], aBase + (uint32_t)mt * 16384u +
                                    ((aoff + ko + a_kof2) ^ swz));
#pragma unroll
                        for (int j = 0; j < 2; j++)
                            ldsm_x4(bfr[nxt][j], bbase + (uint32_t)j * 2048u +
                                    ((ko + b_kof2) ^ swz));
                    }
#pragma unroll
                    for (int mt = 0; mt < 4; mt++)
#pragma unroll
                        for (int nt = 0; nt < 4; nt++)
                            mma16816(acc[mt][nt], afr[cur][mt], &bfr[cur][nt >> 1][(nt & 1) * 2]);
                }

                // ---- tile done: dump to ping-pong stage, reset acc ----------
                if ((ch & 7) == 7) {
                    int slot = nw >> 1;
                    int colbase = (nw & 1) * 32;
                    char* sbase = smem + SM_STAGE + slot * 32768;
#pragma unroll
                    for (int mt = 0; mt < 4; mt++) {
#pragma unroll
                        for (int nt = 0; nt < 4; nt++) {
                            int r0 = mw * 64 + mt * 16 + (lid >> 2);
                            uint32_t cb = (uint32_t)((colbase + nt * 8 + 2 * (lid & 3)) * 4);
                            char* base0 = sbase + r0 * 256;
                            char* base1 = base0 + 8 * 256;
                            *(float2*)(base0 + (cb ^ ((uint32_t)(r0 & 7) << 4))) =
                                make_float2(acc[mt][nt][0], acc[mt][nt][1]);
                            *(float2*)(base1 + (cb ^ ((uint32_t)((r0 + 8) & 7) << 4))) =
                                make_float2(acc[mt][nt][2], acc[mt][nt][3]);
                        }
                    }
#pragma unroll
                    for (int a = 0; a < 4; a++)
#pragma unroll
                        for (int b = 0; b < 4; b++)
#pragma unroll
                            for (int d = 0; d < 4; d++) acc[a][b][d] = 0.f;
                }
            }
            __syncthreads();
        }

        // ---- aux: scan last tile's stage, flush, reset --------------------
        if (is_aux) {
#pragma unroll 1
            for (int s = 0; s < 2; s++) {
                const char* base = smem + SM_STAGE + s * 32768 + r * 256;
                uint32_t rsw = (uint32_t)(r & 7) << 4;
                int rot = r & 15;
#pragma unroll
                for (int jj = 0; jj < 16; jj++) {
                    uint32_t cidx = (uint32_t)((jj + rot) & 15);
                    float4 v = *(const float4*)(base + ((cidx * 16u) ^ rsw));
                    topk_insert(v.x, top, thr);
                    topk_insert(v.y, top, thr);
                    topk_insert(v.z, top, thr);
                    topk_insert(v.w, top, thr);
                }
            }
            int e = c - cta_of_unit(mb << 6);            // < E_SLOTS by construction
            float* dst = g_part + ((size_t)(mb * 128 + r) * E_SLOTS + e) * TOPK;
#pragma unroll
            for (int i = 0; i < TOPK; i++) dst[i] = top[i];
#pragma unroll
            for (int i = 0; i < TOPK; i++) top[i] = -2.0f;
            thr = -2.0f;
        }
        u = seg_end;
    }
}

// ============================================================================
// Kernel 4: merge E_SLOTS partial top-16s -> final sorted weights
// ============================================================================
__global__ void k_merge(float* __restrict__ out) {
    int q = blockIdx.x * blockDim.x + threadIdx.x;
    if (q >= NQ) return;
    float top[TOPK];
#pragma unroll
    for (int i = 0; i < TOPK; i++) top[i] = -2.0f;
    float thr = -2.0f;
    const float4* src = (const float4*)g_part + (size_t)q * (E_SLOTS * TOPK / 4);
#pragma unroll 1
    for (int b = 0; b < E_SLOTS * TOPK / 4; b += 8) {
        float4 v[8];
#pragma unroll
        for (int j = 0; j < 8; j++) v[j] = src[b + j];
#pragma unroll
        for (int j = 0; j < 8; j++) {
            topk_insert(v[j].x, top, thr);
            topk_insert(v[j].y, top, thr);
            topk_insert(v[j].z, top, thr);
            topk_insert(v[j].w, top, thr);
        }
    }
    // sort dots descending (= ascending distance, matching top_k order)
#pragma unroll 1
    for (int a = 0; a < TOPK - 1; a++) {
        int bi = a; float bv = top[a];
#pragma unroll 1
        for (int b = a + 1; b < TOPK; b++)
            if (top[b] > bv) { bv = top[b]; bi = b; }
        top[bi] = top[a]; top[a] = bv;
    }
    float w[TOPK];
    float s = 0.f;
#pragma unroll
    for (int j = 0; j < TOPK; j++) {
        float d2 = fmaxf(2.0f - 2.0f * top[j], 1e-12f);
        float d = sqrtf(d2);
        float wv = expf(-d);
        w[j] = wv; s += wv;
    }
    float inv = 1.0f / fmaxf(s, 1e-12f);
#pragma unroll
    for (int j = 0; j < TOPK; j++) out[(size_t)q * TOPK + j] = w[j] * inv;
}

// ============================================================================
// Launch
// ============================================================================
extern "C" void kernel_launch(void* const* d_in, const int* in_sizes, int n_in,
                              void* d_out, int out_size) {
    const float* x    = (const float*)d_in[0];
    const float* refs = (const float*)d_in[1];
    float* out = (float*)d_out;

    k_norm<<<NQ, 128>>>(x);
    k_cvt<<<2048, 256>>>(refs);
    k_fill<<<(NQ * E_SLOTS * TOPK / 4) / 256, 256>>>();
    cudaFuncSetAttribute(k_main, cudaFuncAttributeMaxDynamicSharedMemorySize, SMEM_TOTAL);
    k_main<<<NCTA, 384, SMEM_TOTAL>>>();
    k_merge<<<NQ / 128, 128>>>(out);
}

// round 10
// speedup vs baseline: 1.5816x; 1.5816x over previous
#include <cuda_runtime.h>
#include <cuda_bf16.h>
#include <cstdint>

// ============================================================================
// Problem constants
// ============================================================================
#define NQ      4096
#define NREF    65536
#define DIMK    512
#define TOPK    16
#define NCTA    148                    // persistent CTAs (one wave)
#define NMB     32                     // query mblocks of 128
#define SPANS_PER_MB 64                // span = 1024 refs = 8 tiles of 128
#define TOTAL_UNITS (NMB * SPANS_PER_MB)   // 2048
#define E_SLOTS 8                      // max CTAs covering one mblock
#define NSQUAD  2                      // scanner threads per query row

// SMEM layout (byte offsets into dynamic smem)
#define SM_A      0                    // 128 x 512 bf16 (swizzled rows)   131072
#define SM_B      131072               // 2 x (128 x 128 bf16 swizzled)     65536
#define SM_STAGE  196608               // 128 x 64 fp32 (swizzled)          32768
#define SM_BAR    229376               // mbar[0],mbar[1] = B bufs; mbar[2] = A
#define SMEM_TOTAL 229408

// ============================================================================
// Scratch (static device arrays; no allocation anywhere)
//   g_refs_sw: tile-swizzled refs:  [tile T:512][kc:4][32KB block]
//              block layout: row*256 + ((col*2) ^ ((row&7)<<4)),  col = k%128
//   g_xn_sw  : swizzled queries:    [mb:32][128KB block]
//              block layout: row*1024 + ((k*2) ^ ((row&7)<<4))
// ============================================================================
__device__ __align__(16) __nv_bfloat16 g_refs_sw[(size_t)NREF * DIMK]; // 64 MB
__device__ __align__(16) __nv_bfloat16 g_xn_sw[(size_t)NQ * DIMK];     // 4 MB
__device__ __align__(16) float g_part[(size_t)NQ * E_SLOTS * NSQUAD * TOPK]; // 4 MB

// ============================================================================
// Helpers (baseline sm_103 ISA only — bulk copy is sm_90 baseline, OK)
// ============================================================================
__device__ __forceinline__ uint32_t smem_u32(const void* p) {
    return (uint32_t)__cvta_generic_to_shared(p);
}

#define MBARRIER_INIT(addr, count) \
    asm volatile("mbarrier.init.shared.b64 [%0], %1;" :: "r"((uint32_t)(addr)), "r"((uint32_t)(count)) : "memory")

#define MBARRIER_EXPECT_TX(addr, bytes) \
    asm volatile("mbarrier.arrive.expect_tx.shared.b64 _, [%0], %1;" \
                 :: "r"((uint32_t)(addr)), "r"((uint32_t)(bytes)) : "memory")

#define MBARRIER_WAIT_PARITY(mbar_smem_addr, phase_parity) do { \
    uint32_t _mbar = (uint32_t)(mbar_smem_addr); \
    uint32_t _parity = (uint32_t)(phase_parity); \
    uint32_t _done; \
    asm volatile( \
        "{\n\t" \
        ".reg .pred p;\n\t" \
        "mbarrier.try_wait.parity.acquire.cta.shared::cta.b64 p, [%1], %2;\n\t" \
        "selp.b32 %0, 1, 0, p;\n\t" \
        "}" \
        : "=r"(_done) : "r"(_mbar), "r"(_parity) : "memory"); \
    if (!_done) { \
        asm volatile( \
            "{\n\t" \
            ".reg .pred P1;\n\t" \
            "WAIT_LOOP_%=:\n\t" \
            "mbarrier.try_wait.parity.acquire.cta.shared::cta.b64 P1, [%0], %1, 0x989680;\n\t" \
            "@P1 bra.uni WAIT_DONE_%=;\n\t" \
            "bra.uni WAIT_LOOP_%=;\n\t" \
            "WAIT_DONE_%=:\n\t" \
            "}" \
            :: "r"(_mbar), "r"(_parity) : "memory"); \
    } \
} while (0)

// One-instruction bulk global->shared copy with mbarrier completion
__device__ __forceinline__ void bulk_g2s(uint32_t dst, const void* src,
                                         uint32_t bytes, uint32_t mbar) {
    asm volatile(
        "cp.async.bulk.shared::cluster.global.mbarrier::complete_tx::bytes [%0], [%1], %2, [%3];"
        :: "r"(dst), "l"((unsigned long long)__cvta_generic_to_global(src)),
           "r"(bytes), "r"(mbar) : "memory");
}

__device__ __forceinline__ void ldsm_x4(uint32_t* r, uint32_t addr) {
    asm volatile("ldmatrix.sync.aligned.m8n8.x4.shared.b16 {%0,%1,%2,%3}, [%4];"
                 : "=r"(r[0]), "=r"(r[1]), "=r"(r[2]), "=r"(r[3]) : "r"(addr));
}

__device__ __forceinline__ void mma16816(float* c, const uint32_t* a, const uint32_t* b) {
    asm volatile("mma.sync.aligned.m16n8k16.row.col.f32.bf16.bf16.f32 "
                 "{%0,%1,%2,%3}, {%4,%5,%6,%7}, {%8,%9}, {%0,%1,%2,%3};"
                 : "+f"(c[0]), "+f"(c[1]), "+f"(c[2]), "+f"(c[3])
                 : "r"(a[0]), "r"(a[1]), "r"(a[2]), "r"(a[3]), "r"(b[0]), "r"(b[1]));
}

__device__ __forceinline__ void topk_insert(float v, float* top, float& thr) {
    if (v > thr) {
        int mi = 0; float mv = top[0];
#pragma unroll
        for (int i = 1; i < TOPK; i++)
            if (top[i] < mv) { mv = top[i]; mi = i; }
        top[mi] = v;
        mv = top[0];
#pragma unroll
        for (int i = 1; i < TOPK; i++) mv = fminf(mv, top[i]);
        thr = mv;
    }
}

// Balanced static partition of TOTAL_UNITS over NCTA CTAs
__device__ __forceinline__ int unit_begin(int c) { return (c * TOTAL_UNITS) / NCTA; }
__device__ __forceinline__ int cta_of_unit(int u) {
    int c = (u * TOTAL_UNITS == 0) ? 0 : (u * NCTA) / TOTAL_UNITS;
    while (unit_begin(c + 1) <= u) c++;
    while (unit_begin(c) > u) c--;
    return c;
}

// ============================================================================
// Kernel 1: L2-normalize x (fp32) -> g_xn_sw (bf16, pre-swizzled layout)
// ============================================================================
__global__ void k_norm(const float* __restrict__ x) {
    int row = blockIdx.x;
    int tid = threadIdx.x;   // 128; thread handles k = 4*tid .. 4*tid+3
    float4 v = ((const float4*)(x + (size_t)row * DIMK))[tid];
    float ss = v.x * v.x + v.y * v.y + v.z * v.z + v.w * v.w;
#pragma unroll
    for (int o = 16; o; o >>= 1) ss += __shfl_xor_sync(0xFFFFFFFFu, ss, o);
    __shared__ float sred[4];
    if ((tid & 31) == 0) sred[tid >> 5] = ss;
    __syncthreads();
    float tot = sred[0] + sred[1] + sred[2] + sred[3];
    float inv = 1.0f / fmaxf(sqrtf(tot), 1e-12f);
    __nv_bfloat162 p0 = __floats2bfloat162_rn(v.x * inv, v.y * inv);
    __nv_bfloat162 p1 = __floats2bfloat162_rn(v.z * inv, v.w * inv);
    int mb = row >> 7, mrow = row & 127;
    uint32_t off = ((uint32_t)(8 * tid)) ^ ((uint32_t)(mrow & 7) << 4);
    char* dst = (char*)g_xn_sw + (size_t)mb * 131072 + (size_t)mrow * 1024 + off;
    uint2 pk;
    pk.x = *(uint32_t*)&p0;
    pk.y = *(uint32_t*)&p1;
    *(uint2*)dst = pk;
}

// ============================================================================
// Kernel 2: refs fp32 -> bf16, written directly in tile-swizzled layout
// ============================================================================
__global__ void k_cvt(const float* __restrict__ refs) {
    int n4 = NREF * DIMK / 4;
    const float4* src = (const float4*)refs;
    for (int i = blockIdx.x * blockDim.x + threadIdx.x; i < n4; i += gridDim.x * blockDim.x) {
        float4 v = src[i];
        int n = i >> 7;            // ref row
        int kq = i & 127;          // float4 index within row (k = 4*kq)
        int T = n >> 7, row = n & 127;
        int kc = kq >> 5;          // 128-col k-block
        uint32_t col2 = (uint32_t)(8 * (kq & 31));
        uint32_t off = col2 ^ ((uint32_t)(row & 7) << 4);
        char* dst = (char*)g_refs_sw + ((size_t)(T * 4 + kc)) * 32768
                  + (size_t)row * 256 + off;
        __nv_bfloat162 p0 = __floats2bfloat162_rn(v.x, v.y);
        __nv_bfloat162 p1 = __floats2bfloat162_rn(v.z, v.w);
        uint2 pk;
        pk.x = *(uint32_t*)&p0;
        pk.y = *(uint32_t*)&p1;
        *(uint2*)dst = pk;
    }
}

// ============================================================================
// Kernel 2b: reset partial-list slots to -2 (required every graph replay)
// ============================================================================
__global__ void k_fill() {
    int i = blockIdx.x * blockDim.x + threadIdx.x;
    ((float4*)g_part)[i] = make_float4(-2.f, -2.f, -2.f, -2.f);
}

// ============================================================================
// Kernel 3: persistent bf16 mma.sync GEMM + fused streaming top-16
//   148 CTAs x 256 threads (8 warps: 2M x 4N of 64x32 warp tiles)
//   B streamed via single-instruction cp.async.bulk (pre-swizzled source)
// ============================================================================
__global__ __launch_bounds__(256, 1) void k_main() {
    extern __shared__ char smem[];
    const uint32_t sb = smem_u32(smem);
    const int tid = threadIdx.x, wid = tid >> 5, lid = tid & 31;
    const int mw = wid >> 2, nw = wid & 3;
    const int c = blockIdx.x;

    // ---- per-lane ldmatrix address components -------------------------------
    const uint32_t swz = (uint32_t)(lid & 7) << 4;
    const int sub = lid >> 3;
    const int aRow = mw * 64 + (lid & 7) + ((sub & 1) << 3);
    const uint32_t a_kof2 = (uint32_t)(sub >> 1) << 4;
    const uint32_t aBase = sb + SM_A + (uint32_t)aRow * 1024u;
    const int bRow = nw * 32 + (lid & 7) + ((sub >> 1) << 3);
    const uint32_t b_kof2 = (uint32_t)(sub & 1) << 4;
    const uint32_t bRowByte = (uint32_t)bRow * 256u;

    const int srow = tid & 127, squad = tid >> 7;        // scanner mapping
    const uint32_t s_swz = (uint32_t)(srow & 7) << 4;

    // ---- mbarrier init ------------------------------------------------------
    if (tid == 0) {
        MBARRIER_INIT(sb + SM_BAR + 0, 1);
        MBARRIER_INIT(sb + SM_BAR + 8, 1);
        MBARRIER_INIT(sb + SM_BAR + 16, 1);
    }
    __syncthreads();
    uint32_t phB0 = 0, phB1 = 0, phA = 0;

    int u = unit_begin(c);
    const int u_end = unit_begin(c + 1);

#pragma unroll 1
    while (u < u_end) {
        const int mb = u >> 6;
        const int seg_end = min(u_end, (mb + 1) << 6);
        const int nch = (seg_end - u) * 32;              // 32 chunks per span
        const int span0 = u & 63;

        // ---- issue A tile bulk + B chunk 0 bulk ------------------------------
        if (tid == 0) {
            MBARRIER_EXPECT_TX(sb + SM_BAR + 16, 131072u);
            bulk_g2s(sb + SM_A, (const char*)g_xn_sw + (size_t)mb * 131072,
                     131072u, sb + SM_BAR + 16);
            int T0 = span0 * 8;                          // chunk 0: tile span0*8, kc 0
            MBARRIER_EXPECT_TX(sb + SM_BAR + 0, 32768u);
            bulk_g2s(sb + SM_B, (const char*)g_refs_sw + ((size_t)T0 * 4) * 32768,
                     32768u, sb + SM_BAR + 0);
        }
        MBARRIER_WAIT_PARITY(sb + SM_BAR + 16, phA);
        phA ^= 1;

        // ---- reinit state ----------------------------------------------------
        float acc[4][4][4];
#pragma unroll
        for (int a = 0; a < 4; a++)
#pragma unroll
            for (int b = 0; b < 4; b++)
#pragma unroll
                for (int d = 0; d < 4; d++) acc[a][b][d] = 0.f;
        float top[TOPK];
#pragma unroll
        for (int i = 0; i < TOPK; i++) top[i] = -2.0f;
        float thr = -2.0f;

#pragma unroll 1
        for (int ch = 0; ch < nch; ch++) {
            // ---- producer: single bulk for chunk ch+1 ------------------------
            if (tid == 0 && ch + 1 < nch) {
                int ch2 = ch + 1;
                int s2 = span0 + (ch2 >> 5);
                int T2 = s2 * 8 + ((ch2 >> 2) & 7);
                int kc2 = ch2 & 3;
                uint32_t mbar = sb + SM_BAR + (uint32_t)(ch2 & 1) * 8u;
                MBARRIER_EXPECT_TX(mbar, 32768u);
                bulk_g2s(sb + SM_B + (uint32_t)(ch2 & 1) * 32768u,
                         (const char*)g_refs_sw + ((size_t)(T2 * 4 + kc2)) * 32768,
                         32768u, mbar);
            }
            // ---- wait current chunk ------------------------------------------
            if (ch & 1) { MBARRIER_WAIT_PARITY(sb + SM_BAR + 8, phB1); phB1 ^= 1; }
            else        { MBARRIER_WAIT_PARITY(sb + SM_BAR + 0, phB0); phB0 ^= 1; }

            // ---- compute chunk ch: K=128 = 8 mma k-steps, sw-pipelined -------
            {
                const uint32_t aoff = (uint32_t)(ch & 3) * 256u;   // k-block in A row
                const uint32_t bbase = sb + SM_B + (uint32_t)(ch & 1) * 32768u + bRowByte;
                uint32_t afr[2][4][4];
                uint32_t bfr[2][2][4];
#pragma unroll
                for (int mt = 0; mt < 4; mt++)
                    ldsm_x4(afr[0][mt], aBase + (uint32_t)mt * 16384u +
                            ((aoff + a_kof2) ^ swz));
#pragma unroll
                for (int j = 0; j < 2; j++)
                    ldsm_x4(bfr[0][j], bbase + (uint32_t)j * 4096u + (b_kof2 ^ swz));
#pragma unroll
                for (int ks = 0; ks < 8; ks++) {
                    const int cur = ks & 1, nxt = cur ^ 1;
                    if (ks < 7) {
                        uint32_t ko = (uint32_t)(ks + 1) * 32u;
#pragma unroll
                        for (int mt = 0; mt < 4; mt++)
                            ldsm_x4(afr[nxt][mt], aBase + (uint32_t)mt * 16384u +
                                    ((aoff + ko + a_kof2) ^ swz));
#pragma unroll
                        for (int j = 0; j < 2; j++)
                            ldsm_x4(bfr[nxt][j], bbase + (uint32_t)j * 4096u +
                                    ((ko + b_kof2) ^ swz));
                    }
#pragma unroll
                    for (int mt = 0; mt < 4; mt++)
#pragma unroll
                        for (int nt = 0; nt < 4; nt++)
                            mma16816(acc[mt][nt], afr[cur][mt], &bfr[cur][nt >> 1][(nt & 1) * 2]);
                }
            }

            // ---- epilogue every 4 chunks (one 128x128 dot tile done) ---------
            if ((ch & 3) == 3) {
#pragma unroll 1
                for (int p = 0; p < 2; p++) {
                    if ((nw >> 1) == p) {
                        int colbase = (nw & 1) * 32;
#pragma unroll
                        for (int mt = 0; mt < 4; mt++) {
#pragma unroll
                            for (int nt = 0; nt < 4; nt++) {
                                int r0 = mw * 64 + mt * 16 + (lid >> 2);
                                uint32_t cb = (uint32_t)((colbase + nt * 8 + 2 * (lid & 3)) * 4);
                                char* base0 = smem + SM_STAGE + r0 * 256;
                                char* base1 = base0 + 8 * 256;
                                *(float2*)(base0 + (cb ^ ((uint32_t)(r0 & 7) << 4))) =
                                    make_float2(acc[mt][nt][0], acc[mt][nt][1]);
                                *(float2*)(base1 + (cb ^ ((uint32_t)((r0 + 8) & 7) << 4))) =
                                    make_float2(acc[mt][nt][2], acc[mt][nt][3]);
                            }
                        }
                    }
                    __syncthreads();
                    {
                        const char* base = smem + SM_STAGE + srow * 256;
#pragma unroll
                        for (int jj = 0; jj < 8; jj++) {
                            uint32_t off = ((uint32_t)(squad * 128 + jj * 16)) ^ s_swz;
                            float4 v = *(const float4*)(base + off);
                            topk_insert(v.x, top, thr);
                            topk_insert(v.y, top, thr);
                            topk_insert(v.z, top, thr);
                            topk_insert(v.w, top, thr);
                        }
                    }
                    __syncthreads();
                }
#pragma unroll
                for (int a = 0; a < 4; a++)
#pragma unroll
                    for (int b = 0; b < 4; b++)
#pragma unroll
                        for (int d = 0; d < 4; d++) acc[a][b][d] = 0.f;
            } else {
                __syncthreads();
            }
        }

        // ---- flush running top-16 for this mblock episode --------------------
        {
            int e = c - cta_of_unit(mb << 6);            // < E_SLOTS by construction
            float* dst = g_part + ((size_t)(mb * 128 + srow) * E_SLOTS + e) * (NSQUAD * TOPK)
                       + squad * TOPK;
#pragma unroll
            for (int i = 0; i < TOPK; i++) dst[i] = top[i];
        }
        u = seg_end;
    }
}

// ============================================================================
// Kernel 4: merge E_SLOTS x NSQUAD partial top-16s -> final sorted weights
// ============================================================================
__global__ void k_merge(float* __restrict__ out) {
    int q = blockIdx.x * blockDim.x + threadIdx.x;
    if (q >= NQ) return;
    float top[TOPK];
#pragma unroll
    for (int i = 0; i < TOPK; i++) top[i] = -2.0f;
    float thr = -2.0f;
    const float4* src = (const float4*)g_part + (size_t)q * (E_SLOTS * NSQUAD * TOPK / 4);
#pragma unroll 1
    for (int b = 0; b < E_SLOTS * NSQUAD * TOPK / 4; b += 8) {
        float4 v[8];
#pragma unroll
        for (int j = 0; j < 8; j++) v[j] = src[b + j];
#pragma unroll
        for (int j = 0; j < 8; j++) {
            topk_insert(v[j].x, top, thr);
            topk_insert(v[j].y, top, thr);
            topk_insert(v[j].z, top, thr);
            topk_insert(v[j].w, top, thr);
        }
    }
    // sort dots descending (= ascending distance, matching top_k order)
#pragma unroll 1
    for (int a = 0; a < TOPK - 1; a++) {
        int bi = a; float bv = top[a];
#pragma unroll 1
        for (int b = a + 1; b < TOPK; b++)
            if (top[b] > bv) { bv = top[b]; bi = b; }
        top[bi] = top[a]; top[a] = bv;
    }
    float w[TOPK];
    float s = 0.f;
#pragma unroll
    for (int j = 0; j < TOPK; j++) {
        float d2 = fmaxf(2.0f - 2.0f * top[j], 1e-12f);
        float d = sqrtf(d2);
        float wv = expf(-d);
        w[j] = wv; s += wv;
    }
    float inv = 1.0f / fmaxf(s, 1e-12f);
#pragma unroll
    for (int j = 0; j < TOPK; j++) out[(size_t)q * TOPK + j] = w[j] * inv;
}

// ============================================================================
// Launch
// ============================================================================
extern "C" void kernel_launch(void* const* d_in, const int* in_sizes, int n_in,
                              void* d_out, int out_size) {
    const float* x    = (const float*)d_in[0];
    const float* refs = (const float*)d_in[1];
    float* out = (float*)d_out;

    k_norm<<<NQ, 128>>>(x);
    k_cvt<<<2048, 256>>>(refs);
    k_fill<<<(NQ * E_SLOTS * NSQUAD * TOPK / 4) / 256, 256>>>();
    cudaFuncSetAttribute(k_main, cudaFuncAttributeMaxDynamicSharedMemorySize, SMEM_TOTAL);
    k_main<<<NCTA, 256, SMEM_TOTAL>>>();
    k_merge<<<NQ / 128, 128>>>(out);
}